// round 1
// baseline (speedup 1.0000x reference)
#include <cuda_runtime.h>
#include <math.h>

#define NF 40
#define DD 64
#define AA 32
#define PP 780
#define XS 68   // padded row stride for x in smem (68 % 32 banks = 4, 16B aligned)
#define WS 68   // padded row stride for W1T in smem

// ---- packed fp32x2 helpers (sm_100+ only; FFMA2 not emitted by ptxas from C++) ----
__device__ __forceinline__ unsigned long long pk2(float lo, float hi) {
    unsigned long long r;
    asm("mov.b64 %0, {%1, %2};" : "=l"(r) : "f"(lo), "f"(hi));
    return r;
}
__device__ __forceinline__ void upk2(unsigned long long v, float& lo, float& hi) {
    asm("mov.b64 {%0, %1}, %2;" : "=f"(lo), "=f"(hi) : "l"(v));
}
__device__ __forceinline__ unsigned long long mul2(unsigned long long a, unsigned long long b) {
    unsigned long long r;
    asm("mul.rn.f32x2 %0, %1, %2;" : "=l"(r) : "l"(a), "l"(b));
    return r;
}
__device__ __forceinline__ void fma2(unsigned long long& c, unsigned long long a, unsigned long long b) {
    asm("fma.rn.f32x2 %0, %1, %2, %3;" : "=l"(c) : "l"(a), "l"(b), "l"(c));
}

__global__ __launch_bounds__(256, 2)
void afm_kernel(const float* __restrict__ x,
                const float* __restrict__ W1,
                const float* __restrict__ b1,
                const float* __restrict__ w2,
                const float* __restrict__ pvec,
                float* __restrict__ out)
{
    __shared__ float sx[NF * XS];      // x tile, padded rows
    __shared__ float sW[AA * WS];      // W1 transposed: sW[a*WS + d]
    __shared__ float sb1[AA];
    __shared__ float sw2[AA];
    __shared__ float sp[DD];
    __shared__ float slog[PP];
    __shared__ float ss[PP];
    __shared__ float red[32];

    const int b   = blockIdx.x;
    const int tid = threadIdx.x;
    const int lane = tid & 31;
    const int wid  = tid >> 5;

    // ---- stage inputs ----
    const float* xb = x + (size_t)b * (NF * DD);
    #pragma unroll
    for (int t = tid; t < NF * DD; t += 256) {
        int f = t >> 6, d = t & 63;
        sx[f * XS + d] = xb[t];
    }
    // W1 is [64][32] row-major (d-major); store transposed sW[a][d]
    for (int t = tid; t < DD * AA; t += 256) {
        int d = t >> 5, a = t & 31;
        sW[a * WS + d] = W1[t];
    }
    if (tid < AA) { sb1[tid] = b1[tid]; sw2[tid] = w2[tid]; }
    if (tid < DD) sp[tid] = pvec[tid];
    __syncthreads();

    const ulonglong2* sp2 = (const ulonglong2*)sp;

    // ---- pass 1: per-pair logit + s_p = prod . p ----
    float lmax = -INFINITY;
    for (int pp = tid; pp < PP; pp += 256) {
        // map pair index -> (i, j), matching np.triu_indices(40, k=1) order
        int rem = pp, i = 0, span = NF - 1;
        while (rem >= span) { rem -= span; i++; span--; }
        int j = i + 1 + rem;

        const ulonglong2* xi = (const ulonglong2*)(sx + i * XS);
        const ulonglong2* xj = (const ulonglong2*)(sx + j * XS);

        unsigned long long prod[DD / 2];
        #pragma unroll
        for (int k = 0; k < DD / 4; k++) {
            ulonglong2 av = xi[k];
            ulonglong2 bv = xj[k];
            prod[2 * k]     = mul2(av.x, bv.x);
            prod[2 * k + 1] = mul2(av.y, bv.y);
        }

        // s_p = prod . p  (packed)
        unsigned long long sacc = 0ULL;   // (+0.0f, +0.0f)
        #pragma unroll
        for (int k = 0; k < DD / 4; k++) {
            ulonglong2 pv = sp2[k];
            fma2(sacc, prod[2 * k],     pv.x);
            fma2(sacc, prod[2 * k + 1], pv.y);
        }
        float s_lo, s_hi;
        upk2(sacc, s_lo, s_hi);

        // logit = w2 . relu(prod @ W1 + b1)
        float logit = 0.0f;
        #pragma unroll 4
        for (int a = 0; a < AA; a++) {
            const ulonglong2* wrow = (const ulonglong2*)(sW + a * WS);
            unsigned long long acc = pk2(sb1[a], 0.0f);
            #pragma unroll
            for (int k = 0; k < DD / 4; k++) {
                ulonglong2 wv = wrow[k];
                fma2(acc, prod[2 * k],     wv.x);
                fma2(acc, prod[2 * k + 1], wv.y);
            }
            float h_lo, h_hi;
            upk2(acc, h_lo, h_hi);
            float h = h_lo + h_hi;
            h = fmaxf(h, 0.0f);
            logit = fmaf(h, sw2[a], logit);
        }

        slog[pp] = logit;
        ss[pp]   = s_lo + s_hi;
        lmax = fmaxf(lmax, logit);
    }

    // ---- block max reduction ----
    #pragma unroll
    for (int o = 16; o > 0; o >>= 1)
        lmax = fmaxf(lmax, __shfl_xor_sync(0xFFFFFFFFu, lmax, o));
    if (lane == 0) red[wid] = lmax;
    __syncthreads();
    if (tid == 0) {
        float m = red[0];
        #pragma unroll
        for (int w = 1; w < 8; w++) m = fmaxf(m, red[w]);
        red[16] = m;
    }
    __syncthreads();
    const float mx = red[16];

    // ---- softmax-weighted scalar accumulation ----
    float num = 0.0f, den = 0.0f;
    for (int pp = tid; pp < PP; pp += 256) {
        float e = __expf(slog[pp] - mx);
        num = fmaf(e, ss[pp], num);
        den += e;
    }
    #pragma unroll
    for (int o = 16; o > 0; o >>= 1) {
        num += __shfl_xor_sync(0xFFFFFFFFu, num, o);
        den += __shfl_xor_sync(0xFFFFFFFFu, den, o);
    }
    __syncthreads();   // red[] reuse safety
    if (lane == 0) { red[wid] = num; red[8 + wid] = den; }
    __syncthreads();
    if (tid == 0) {
        float n = 0.0f, d = 0.0f;
        #pragma unroll
        for (int w = 0; w < 8; w++) { n += red[w]; d += red[8 + w]; }
        out[b] = n / d;
    }
}

extern "C" void kernel_launch(void* const* d_in, const int* in_sizes, int n_in,
                              void* d_out, int out_size)
{
    const float* x    = (const float*)d_in[0];
    const float* W1   = (const float*)d_in[1];
    const float* b1   = (const float*)d_in[2];
    const float* w2   = (const float*)d_in[3];
    const float* pvec = (const float*)d_in[4];
    float* out = (float*)d_out;

    int B = in_sizes[0] / (NF * DD);
    afm_kernel<<<B, 256>>>(x, W1, b1, w2, pvec, out);
}

// round 2
// speedup vs baseline: 2.1266x; 2.1266x over previous
#include <cuda_runtime.h>
#include <math.h>

#define NF   40
#define DD   64
#define AA   32
#define PPV  780      // valid pairs
#define PADP 896      // padded pairs (7 * 128)
#define TR   128      // pair-tile rows
#define NT   5        // n8 tiles (40 cols: 32 a + 1 s + 7 pad)
#define XS   68       // sx row stride (floats)
#define PS   68       // sprod row stride (floats) -> conflict-free A-frag loads
#define WTS  40       // sWt row stride -> conflict-free B-frag loads

// smem layout (in floats)
#define OFF_SX    0                       // 40*68   = 2720
#define OFF_SWT   (OFF_SX + NF*XS)        // 64*40   = 2560 (tf32 bits)
#define OFF_B1E   (OFF_SWT + DD*WTS)      // 48
#define OFF_W2E   (OFF_B1E + 48)          // 48
#define OFF_PI    (OFF_W2E + 48)          // 896 ints
#define OFF_PJ    (OFF_PI + PADP)         // 896 ints
#define OFF_SLOG  (OFF_PJ + PADP)         // 780
#define OFF_SS    (OFF_SLOG + PPV)        // 780
#define OFF_RED   (OFF_SS + PPV)          // 32
#define OFF_PROD  (((OFF_RED + 32) + 3) & ~3)   // 128*68 = 8704 (tf32 bits), 16B aligned
#define SMEM_FLOATS (OFF_PROD + TR*PS)
#define SMEM_BYTES  (SMEM_FLOATS * 4)

__device__ __forceinline__ unsigned f2tf(float f) {
    unsigned u;
    asm("cvt.rna.tf32.f32 %0, %1;" : "=r"(u) : "f"(f));
    return u;
}

__device__ __forceinline__ void mma_tf32(float c[4],
                                         unsigned a0, unsigned a1, unsigned a2, unsigned a3,
                                         unsigned b0, unsigned b1) {
    asm("mma.sync.aligned.m16n8k8.row.col.f32.tf32.tf32.f32 "
        "{%0,%1,%2,%3}, {%4,%5,%6,%7}, {%8,%9}, {%0,%1,%2,%3};"
        : "+f"(c[0]), "+f"(c[1]), "+f"(c[2]), "+f"(c[3])
        : "r"(a0), "r"(a1), "r"(a2), "r"(a3), "r"(b0), "r"(b1));
}

__global__ __launch_bounds__(256, 2)
void afm_kernel(const float* __restrict__ x,
                const float* __restrict__ W1,
                const float* __restrict__ b1,
                const float* __restrict__ w2,
                const float* __restrict__ pvec,
                float* __restrict__ out)
{
    extern __shared__ float sm[];
    float*    sx    = sm + OFF_SX;
    unsigned* sWt   = (unsigned*)(sm + OFF_SWT);
    float*    b1e   = sm + OFF_B1E;
    float*    w2e   = sm + OFF_W2E;
    int*      spi   = (int*)(sm + OFF_PI);
    int*      spj   = (int*)(sm + OFF_PJ);
    float*    slog  = sm + OFF_SLOG;
    float*    ss    = sm + OFF_SS;
    float*    red   = sm + OFF_RED;
    unsigned* sprod = (unsigned*)(sm + OFF_PROD);

    const int b    = blockIdx.x;
    const int tid  = threadIdx.x;
    const int lane = tid & 31;
    const int wrp  = tid >> 5;
    const int gid  = lane >> 2;   // 0..7
    const int tig  = lane & 3;    // 0..3

    // ---- stage x ----
    const float* xb = x + (size_t)b * (NF * DD);
    #pragma unroll
    for (int t = tid; t < NF * DD; t += 256) {
        int f = t >> 6, d = t & 63;
        sx[f * XS + d] = xb[t];
    }
    // ---- W-tilde [64][40]: cols 0..31 = W1, col 32 = p, 33..39 = 0 (tf32 bits) ----
    for (int t = tid; t < DD * WTS; t += 256) {
        int k = t / WTS, n = t - k * WTS;
        float v = (n < AA) ? W1[k * AA + n] : (n == AA ? pvec[k] : 0.0f);
        sWt[k * WTS + n] = f2tf(v);
    }
    if (tid < 48) {
        b1e[tid] = (tid < AA) ? b1[tid] : 0.0f;
        w2e[tid] = (tid < AA) ? w2[tid] : 0.0f;
    }
    // ---- pair index tables ----
    for (int pp = tid; pp < PADP; pp += 256) {
        int i = 0, j = 0;
        if (pp < PPV) {
            int rem = pp, span = NF - 1;
            while (rem >= span) { rem -= span; i++; span--; }
            j = i + 1 + rem;
        }
        spi[pp] = i; spj[pp] = j;
    }
    __syncthreads();

    // ---- tiles of 128 pairs: prod gen -> tf32 MMA -> epilogue ----
    for (int t = 0; t < PADP / TR; t++) {
        const int p0 = t * TR;
        if (t > 0) __syncthreads();          // previous epilogue done reading sprod

        // prod generation: thread -> (row = tid>>1, half = tid&1), 32 cols
        {
            int r = tid >> 1, h = tid & 1;
            int pp = p0 + r;
            const float4* xi = (const float4*)(sx + spi[pp] * XS + 32 * h);
            const float4* xj = (const float4*)(sx + spj[pp] * XS + 32 * h);
            uint4* dst = (uint4*)(sprod + r * PS + 32 * h);
            #pragma unroll
            for (int m = 0; m < 8; m++) {
                float4 a = xi[m], c = xj[m];
                uint4 o;
                o.x = f2tf(a.x * c.x);
                o.y = f2tf(a.y * c.y);
                o.z = f2tf(a.z * c.z);
                o.w = f2tf(a.w * c.w);
                dst[m] = o;
            }
        }
        __syncthreads();

        // MMA: warp wrp owns rows [wrp*16, wrp*16+16)
        float acc[NT][4];
        #pragma unroll
        for (int n = 0; n < NT; n++)
            #pragma unroll
            for (int q = 0; q < 4; q++) acc[n][q] = 0.0f;

        const int row0 = wrp * 16 + gid;
        #pragma unroll
        for (int k0 = 0; k0 < DD; k0 += 8) {
            unsigned a0 = sprod[row0 * PS + k0 + tig];
            unsigned a1 = sprod[(row0 + 8) * PS + k0 + tig];
            unsigned a2 = sprod[row0 * PS + k0 + tig + 4];
            unsigned a3 = sprod[(row0 + 8) * PS + k0 + tig + 4];
            #pragma unroll
            for (int n = 0; n < NT; n++) {
                unsigned b0 = sWt[(k0 + tig) * WTS + n * 8 + gid];
                unsigned bq = sWt[(k0 + tig + 4) * WTS + n * 8 + gid];
                mma_tf32(acc[n], a0, a1, a2, a3, b0, bq);
            }
        }

        // epilogue: logit = sum_a relu(c + b1)*w2 ; s from col 32
        float ls0 = 0.0f, ls1 = 0.0f, s0 = 0.0f, s1 = 0.0f;
        #pragma unroll
        for (int n = 0; n < NT; n++) {
            float bb0 = b1e[n * 8 + 2 * tig], bb1 = b1e[n * 8 + 2 * tig + 1];
            float ww0 = w2e[n * 8 + 2 * tig], ww1 = w2e[n * 8 + 2 * tig + 1];
            ls0 += fmaxf(acc[n][0] + bb0, 0.0f) * ww0 + fmaxf(acc[n][1] + bb1, 0.0f) * ww1;
            ls1 += fmaxf(acc[n][2] + bb0, 0.0f) * ww0 + fmaxf(acc[n][3] + bb1, 0.0f) * ww1;
        }
        if (tig == 0) { s0 = acc[4][0]; s1 = acc[4][2]; }   // col 32 = prod . p
        ls0 += __shfl_xor_sync(0xFFFFFFFFu, ls0, 1);
        ls0 += __shfl_xor_sync(0xFFFFFFFFu, ls0, 2);
        ls1 += __shfl_xor_sync(0xFFFFFFFFu, ls1, 1);
        ls1 += __shfl_xor_sync(0xFFFFFFFFu, ls1, 2);
        if (tig == 0) {
            int pr0 = p0 + row0;
            if (pr0 < PPV)     { slog[pr0] = ls0;     ss[pr0] = s0; }
            if (pr0 + 8 < PPV) { slog[pr0 + 8] = ls1; ss[pr0 + 8] = s1; }
        }
    }
    __syncthreads();

    // ---- softmax over 780 pairs + weighted sum ----
    float lmax = -INFINITY;
    for (int pp = tid; pp < PPV; pp += 256) lmax = fmaxf(lmax, slog[pp]);
    #pragma unroll
    for (int o = 16; o > 0; o >>= 1)
        lmax = fmaxf(lmax, __shfl_xor_sync(0xFFFFFFFFu, lmax, o));
    if (lane == 0) red[wrp] = lmax;
    __syncthreads();
    if (tid == 0) {
        float m = red[0];
        #pragma unroll
        for (int w = 1; w < 8; w++) m = fmaxf(m, red[w]);
        red[16] = m;
    }
    __syncthreads();
    const float mx = red[16];

    float num = 0.0f, den = 0.0f;
    for (int pp = tid; pp < PPV; pp += 256) {
        float e = __expf(slog[pp] - mx);
        num = fmaf(e, ss[pp], num);
        den += e;
    }
    #pragma unroll
    for (int o = 16; o > 0; o >>= 1) {
        num += __shfl_xor_sync(0xFFFFFFFFu, num, o);
        den += __shfl_xor_sync(0xFFFFFFFFu, den, o);
    }
    __syncthreads();
    if (lane == 0) { red[wrp] = num; red[8 + wrp] = den; }
    __syncthreads();
    if (tid == 0) {
        float n = 0.0f, d = 0.0f;
        #pragma unroll
        for (int w = 0; w < 8; w++) { n += red[w]; d += red[8 + w]; }
        out[b] = n / d;
    }
}

extern "C" void kernel_launch(void* const* d_in, const int* in_sizes, int n_in,
                              void* d_out, int out_size)
{
    const float* x    = (const float*)d_in[0];
    const float* W1   = (const float*)d_in[1];
    const float* b1   = (const float*)d_in[2];
    const float* w2   = (const float*)d_in[3];
    const float* pvec = (const float*)d_in[4];
    float* out = (float*)d_out;

    cudaFuncSetAttribute(afm_kernel, cudaFuncAttributeMaxDynamicSharedMemorySize, SMEM_BYTES);

    int B = in_sizes[0] / (NF * DD);
    afm_kernel<<<B, 256, SMEM_BYTES>>>(x, W1, b1, w2, pvec, out);
}

// round 3
// speedup vs baseline: 2.5269x; 1.1882x over previous
#include <cuda_runtime.h>
#include <math.h>

#define NF   40
#define DD   64
#define AA   32
#define PPV  780      // valid pairs
#define PADP 896      // padded pairs (7 * 128)
#define TR   128      // pair-tile rows
#define NT   4        // n8 tiles (32 attn cols)
#define XS   68       // sx row stride (floats), 16B aligned
#define WTS  40       // sWt row stride (conflict-free B loads)

__device__ __forceinline__ unsigned f2tf(float f) {
    unsigned u;
    asm("cvt.rna.tf32.f32 %0, %1;" : "=r"(u) : "f"(f));
    return u;
}

__device__ __forceinline__ void mma_tf32(float c[4],
                                         unsigned a0, unsigned a1, unsigned a2, unsigned a3,
                                         unsigned b0, unsigned b1) {
    asm("mma.sync.aligned.m16n8k8.row.col.f32.tf32.tf32.f32 "
        "{%0,%1,%2,%3}, {%4,%5,%6,%7}, {%8,%9}, {%0,%1,%2,%3};"
        : "+f"(c[0]), "+f"(c[1]), "+f"(c[2]), "+f"(c[3])
        : "r"(a0), "r"(a1), "r"(a2), "r"(a3), "r"(b0), "r"(b1));
}

__global__ __launch_bounds__(256, 1)
void afm_kernel(const float* __restrict__ x,
                const float* __restrict__ W1,
                const float* __restrict__ b1,
                const float* __restrict__ w2,
                const float* __restrict__ pvec,
                float* __restrict__ out)
{
    // k-permuted x: sx[f*XS + (k&3)*16 + (k>>2)]  ->  one LDS.128 = 4 perm-consecutive
    // values = (a0,a2) fragments for two adjacent k8-groups.
    __shared__ float    sx[NF * XS];        // 2720
    __shared__ unsigned sWt[DD * WTS];      // W-tilde tf32 bits, [k][n]
    __shared__ float    spp[DD];            // permuted p vector
    __shared__ float    sb1[AA], sw2[AA];
    __shared__ int      spi[PADP], spj[PADP];
    __shared__ float    slog[PPV], ssv[PPV];
    __shared__ float    red[32];

    const int b    = blockIdx.x;
    const int tid  = threadIdx.x;
    const int lane = tid & 31;
    const int wrp  = tid >> 5;
    const int gid  = lane >> 2;   // 0..7
    const int tig  = lane & 3;    // 0..3

    // ---- stage permuted x ----
    const float* xb = x + (size_t)b * (NF * DD);
    #pragma unroll
    for (int t = tid; t < NF * DD; t += 256) {
        int f = t >> 6, k = t & 63;
        sx[f * XS + ((k & 3) << 4) + (k >> 2)] = xb[t];
    }
    // ---- W1 as tf32 [k][n] ----
    for (int t = tid; t < DD * AA; t += 256) {
        int k = t >> 5, n = t & 31;
        sWt[k * WTS + n] = f2tf(W1[t]);
    }
    if (tid < DD) spp[((tid & 3) << 4) + (tid >> 2)] = pvec[tid];
    if (tid < AA) { sb1[tid] = b1[tid]; sw2[tid] = w2[tid]; }
    // ---- pair tables ----
    for (int pp = tid; pp < PADP; pp += 256) {
        int i = 0, j = 0;
        if (pp < PPV) {
            int rem = pp, span = NF - 1;
            while (rem >= span) { rem -= span; i++; span--; }
            j = i + 1 + rem;
        }
        spi[pp] = i; spj[pp] = j;
    }
    __syncthreads();

    // ---- hoist B fragments + epilogue constants into registers (per-CTA reuse) ----
    unsigned Bv[8][NT][2];
    #pragma unroll
    for (int g = 0; g < 8; g++)
        #pragma unroll
        for (int n = 0; n < NT; n++) {
            Bv[g][n][0] = sWt[(8 * g + tig) * WTS + n * 8 + gid];
            Bv[g][n][1] = sWt[(8 * g + tig + 4) * WTS + n * 8 + gid];
        }
    float bb[NT][2], ww[NT][2];
    #pragma unroll
    for (int n = 0; n < NT; n++) {
        bb[n][0] = sb1[n * 8 + 2 * tig]; bb[n][1] = sb1[n * 8 + 2 * tig + 1];
        ww[n][0] = sw2[n * 8 + 2 * tig]; ww[n][1] = sw2[n * 8 + 2 * tig + 1];
    }
    const float4* spp4 = (const float4*)spp;
    const int row0 = wrp * 16 + gid;

    // ---- 7 tiles of 128 pairs; no smem prod, no intra-loop barriers ----
    #pragma unroll 1
    for (int t = 0; t < PADP / TR; t++) {
        const int p0 = t * TR;
        const int pA = p0 + row0;
        const float4* xi0 = (const float4*)(sx + spi[pA] * XS);
        const float4* xj0 = (const float4*)(sx + spj[pA] * XS);
        const float4* xi1 = (const float4*)(sx + spi[pA + 8] * XS);
        const float4* xj1 = (const float4*)(sx + spj[pA + 8] * XS);

        float acc[NT][4];
        #pragma unroll
        for (int n = 0; n < NT; n++)
            { acc[n][0] = acc[n][1] = acc[n][2] = acc[n][3] = 0.0f; }
        float s0 = 0.0f, s1 = 0.0f;

        #pragma unroll
        for (int q = 0; q < 4; q++) {
            const int c = tig * 4 + q;
            float4 vi0 = xi0[c], vj0 = xj0[c];
            float4 vi1 = xi1[c], vj1 = xj1[c];
            float4 pv  = spp4[c];

            float p00 = vi0.x * vj0.x, p01 = vi0.y * vj0.y;
            float p02 = vi0.z * vj0.z, p03 = vi0.w * vj0.w;
            float p10 = vi1.x * vj1.x, p11 = vi1.y * vj1.y;
            float p12 = vi1.z * vj1.z, p13 = vi1.w * vj1.w;

            s0 = fmaf(p00, pv.x, fmaf(p01, pv.y, fmaf(p02, pv.z, fmaf(p03, pv.w, s0))));
            s1 = fmaf(p10, pv.x, fmaf(p11, pv.y, fmaf(p12, pv.z, fmaf(p13, pv.w, s1))));

            unsigned a0 = f2tf(p00), a2 = f2tf(p01);
            unsigned a1 = f2tf(p10), a3 = f2tf(p11);
            #pragma unroll
            for (int n = 0; n < NT; n++)
                mma_tf32(acc[n], a0, a1, a2, a3, Bv[2 * q][n][0], Bv[2 * q][n][1]);

            a0 = f2tf(p02); a2 = f2tf(p03);
            a1 = f2tf(p12); a3 = f2tf(p13);
            #pragma unroll
            for (int n = 0; n < NT; n++)
                mma_tf32(acc[n], a0, a1, a2, a3, Bv[2 * q + 1][n][0], Bv[2 * q + 1][n][1]);
        }

        // epilogue: logit = sum_a relu(c + b1)*w2 ; s = quad-reduced prod.p
        float ls0 = 0.0f, ls1 = 0.0f;
        #pragma unroll
        for (int n = 0; n < NT; n++) {
            ls0 += fmaxf(acc[n][0] + bb[n][0], 0.0f) * ww[n][0]
                 + fmaxf(acc[n][1] + bb[n][1], 0.0f) * ww[n][1];
            ls1 += fmaxf(acc[n][2] + bb[n][0], 0.0f) * ww[n][0]
                 + fmaxf(acc[n][3] + bb[n][1], 0.0f) * ww[n][1];
        }
        ls0 += __shfl_xor_sync(0xFFFFFFFFu, ls0, 1);
        ls0 += __shfl_xor_sync(0xFFFFFFFFu, ls0, 2);
        ls1 += __shfl_xor_sync(0xFFFFFFFFu, ls1, 1);
        ls1 += __shfl_xor_sync(0xFFFFFFFFu, ls1, 2);
        s0  += __shfl_xor_sync(0xFFFFFFFFu, s0, 1);
        s0  += __shfl_xor_sync(0xFFFFFFFFu, s0, 2);
        s1  += __shfl_xor_sync(0xFFFFFFFFu, s1, 1);
        s1  += __shfl_xor_sync(0xFFFFFFFFu, s1, 2);
        if (tig == 0) {
            if (pA < PPV)     { slog[pA] = ls0;     ssv[pA] = s0; }
            if (pA + 8 < PPV) { slog[pA + 8] = ls1; ssv[pA + 8] = s1; }
        }
    }
    __syncthreads();

    // ---- softmax over 780 pairs + weighted sum ----
    float lmax = -INFINITY;
    for (int pp = tid; pp < PPV; pp += 256) lmax = fmaxf(lmax, slog[pp]);
    #pragma unroll
    for (int o = 16; o > 0; o >>= 1)
        lmax = fmaxf(lmax, __shfl_xor_sync(0xFFFFFFFFu, lmax, o));
    if (lane == 0) red[wrp] = lmax;
    __syncthreads();
    if (tid == 0) {
        float m = red[0];
        #pragma unroll
        for (int w = 1; w < 8; w++) m = fmaxf(m, red[w]);
        red[16] = m;
    }
    __syncthreads();
    const float mx = red[16];

    float num = 0.0f, den = 0.0f;
    for (int pp = tid; pp < PPV; pp += 256) {
        float e = __expf(slog[pp] - mx);
        num = fmaf(e, ssv[pp], num);
        den += e;
    }
    #pragma unroll
    for (int o = 16; o > 0; o >>= 1) {
        num += __shfl_xor_sync(0xFFFFFFFFu, num, o);
        den += __shfl_xor_sync(0xFFFFFFFFu, den, o);
    }
    __syncthreads();
    if (lane == 0) { red[wrp] = num; red[8 + wrp] = den; }
    __syncthreads();
    if (tid == 0) {
        float n = 0.0f, d = 0.0f;
        #pragma unroll
        for (int w = 0; w < 8; w++) { n += red[w]; d += red[8 + w]; }
        out[b] = n / d;
    }
}

extern "C" void kernel_launch(void* const* d_in, const int* in_sizes, int n_in,
                              void* d_out, int out_size)
{
    const float* x    = (const float*)d_in[0];
    const float* W1   = (const float*)d_in[1];
    const float* b1   = (const float*)d_in[2];
    const float* w2   = (const float*)d_in[3];
    const float* pvec = (const float*)d_in[4];
    float* out = (float*)d_out;

    int B = in_sizes[0] / (NF * DD);
    afm_kernel<<<B, 256>>>(x, W1, b1, w2, pvec, out);
}

// round 4
// speedup vs baseline: 2.8244x; 1.1178x over previous
#include <cuda_runtime.h>
#include <math.h>

#define NF   40
#define DD   64
#define AA   32
#define PPV  780      // valid pairs
#define NTH  192      // threads per CTA (6 warps)
#define NW   6
#define TR   96       // pair-tile rows (6 warps x 16)
#define NTILE 9
#define PADP (TR * NTILE)   // 864
#define NT   4        // n8 tiles (32 attn cols)
#define XS   68       // sx row stride (floats), 16B aligned
#define WTS  40       // sWt row stride (conflict-free B loads)

__device__ __forceinline__ unsigned f2tf(float f) {
    unsigned u;
    asm("cvt.rna.tf32.f32 %0, %1;" : "=r"(u) : "f"(f));
    return u;
}

__device__ __forceinline__ void mma_tf32(float c[4],
                                         unsigned a0, unsigned a1, unsigned a2, unsigned a3,
                                         unsigned b0, unsigned b1) {
    asm("mma.sync.aligned.m16n8k8.row.col.f32.tf32.tf32.f32 "
        "{%0,%1,%2,%3}, {%4,%5,%6,%7}, {%8,%9}, {%0,%1,%2,%3};"
        : "+f"(c[0]), "+f"(c[1]), "+f"(c[2]), "+f"(c[3])
        : "r"(a0), "r"(a1), "r"(a2), "r"(a3), "r"(b0), "r"(b1));
}

__global__ __launch_bounds__(NTH, 2)
void afm_kernel(const float* __restrict__ x,
                const float* __restrict__ W1,
                const float* __restrict__ b1,
                const float* __restrict__ w2,
                const float* __restrict__ pvec,
                float* __restrict__ out)
{
    // k-permuted x: sx[f*XS + (k&3)*16 + (k>>2)]  ->  one LDS.128 = 4 perm-consecutive
    // values = (a0,a2) fragments for two adjacent k8-groups.
    __shared__ float    sx[NF * XS];
    __shared__ unsigned sWt[DD * WTS];      // W1 tf32 bits, [k][n]
    __shared__ float    spp[DD];            // permuted p vector
    __shared__ float    sb1[AA], sw2[AA];
    __shared__ int      spi[PADP], spj[PADP];
    __shared__ float    slog[PPV], ssv[PPV];
    __shared__ float    red[32];

    const int b    = blockIdx.x;
    const int tid  = threadIdx.x;
    const int lane = tid & 31;
    const int wrp  = tid >> 5;
    const int gid  = lane >> 2;   // 0..7
    const int tig  = lane & 3;    // 0..3

    // ---- stage permuted x ----
    const float* xb = x + (size_t)b * (NF * DD);
    for (int t = tid; t < NF * DD; t += NTH) {
        int f = t >> 6, k = t & 63;
        sx[f * XS + ((k & 3) << 4) + (k >> 2)] = xb[t];
    }
    // ---- W1 as tf32 [k][n] ----
    for (int t = tid; t < DD * AA; t += NTH) {
        int k = t >> 5, n = t & 31;
        sWt[k * WTS + n] = f2tf(W1[t]);
    }
    if (tid < DD) spp[((tid & 3) << 4) + (tid >> 2)] = pvec[tid];
    if (tid < AA) { sb1[tid] = b1[tid]; sw2[tid] = w2[tid]; }
    // ---- pair tables ----
    for (int pp = tid; pp < PADP; pp += NTH) {
        int i = 0, j = 0;
        if (pp < PPV) {
            int rem = pp, span = NF - 1;
            while (rem >= span) { rem -= span; i++; span--; }
            j = i + 1 + rem;
        }
        spi[pp] = i; spj[pp] = j;
    }
    __syncthreads();

    // ---- hoist B fragments + epilogue constants into registers (per-CTA reuse) ----
    unsigned Bv[8][NT][2];
    #pragma unroll
    for (int g = 0; g < 8; g++)
        #pragma unroll
        for (int n = 0; n < NT; n++) {
            Bv[g][n][0] = sWt[(8 * g + tig) * WTS + n * 8 + gid];
            Bv[g][n][1] = sWt[(8 * g + tig + 4) * WTS + n * 8 + gid];
        }
    float bb[NT][2], ww[NT][2];
    #pragma unroll
    for (int n = 0; n < NT; n++) {
        bb[n][0] = sb1[n * 8 + 2 * tig]; bb[n][1] = sb1[n * 8 + 2 * tig + 1];
        ww[n][0] = sw2[n * 8 + 2 * tig]; ww[n][1] = sw2[n * 8 + 2 * tig + 1];
    }
    const float4* spp4 = (const float4*)spp;
    const int row0 = wrp * 16 + gid;

    // ---- 9 tiles of 96 pairs; no smem prod, no intra-loop barriers ----
    #pragma unroll 1
    for (int t = 0; t < NTILE; t++) {
        const int p0 = t * TR;
        const int pA = p0 + row0;
        const float4* xi0 = (const float4*)(sx + spi[pA] * XS);
        const float4* xj0 = (const float4*)(sx + spj[pA] * XS);
        const float4* xi1 = (const float4*)(sx + spi[pA + 8] * XS);
        const float4* xj1 = (const float4*)(sx + spj[pA + 8] * XS);

        float acc[NT][4];
        #pragma unroll
        for (int n = 0; n < NT; n++)
            { acc[n][0] = acc[n][1] = acc[n][2] = acc[n][3] = 0.0f; }
        float s0 = 0.0f, s1 = 0.0f;

        #pragma unroll
        for (int q = 0; q < 4; q++) {
            const int c = tig * 4 + q;
            float4 vi0 = xi0[c], vj0 = xj0[c];
            float4 vi1 = xi1[c], vj1 = xj1[c];
            float4 pv  = spp4[c];

            float p00 = vi0.x * vj0.x, p01 = vi0.y * vj0.y;
            float p02 = vi0.z * vj0.z, p03 = vi0.w * vj0.w;
            float p10 = vi1.x * vj1.x, p11 = vi1.y * vj1.y;
            float p12 = vi1.z * vj1.z, p13 = vi1.w * vj1.w;

            s0 = fmaf(p00, pv.x, fmaf(p01, pv.y, fmaf(p02, pv.z, fmaf(p03, pv.w, s0))));
            s1 = fmaf(p10, pv.x, fmaf(p11, pv.y, fmaf(p12, pv.z, fmaf(p13, pv.w, s1))));

            unsigned a0 = f2tf(p00), a2 = f2tf(p01);
            unsigned a1 = f2tf(p10), a3 = f2tf(p11);
            #pragma unroll
            for (int n = 0; n < NT; n++)
                mma_tf32(acc[n], a0, a1, a2, a3, Bv[2 * q][n][0], Bv[2 * q][n][1]);

            a0 = f2tf(p02); a2 = f2tf(p03);
            a1 = f2tf(p12); a3 = f2tf(p13);
            #pragma unroll
            for (int n = 0; n < NT; n++)
                mma_tf32(acc[n], a0, a1, a2, a3, Bv[2 * q + 1][n][0], Bv[2 * q + 1][n][1]);
        }

        // epilogue: logit = sum_a relu(c + b1)*w2 ; s = quad-reduced prod.p
        float ls0 = 0.0f, ls1 = 0.0f;
        #pragma unroll
        for (int n = 0; n < NT; n++) {
            ls0 += fmaxf(acc[n][0] + bb[n][0], 0.0f) * ww[n][0]
                 + fmaxf(acc[n][1] + bb[n][1], 0.0f) * ww[n][1];
            ls1 += fmaxf(acc[n][2] + bb[n][0], 0.0f) * ww[n][0]
                 + fmaxf(acc[n][3] + bb[n][1], 0.0f) * ww[n][1];
        }
        ls0 += __shfl_xor_sync(0xFFFFFFFFu, ls0, 1);
        ls0 += __shfl_xor_sync(0xFFFFFFFFu, ls0, 2);
        ls1 += __shfl_xor_sync(0xFFFFFFFFu, ls1, 1);
        ls1 += __shfl_xor_sync(0xFFFFFFFFu, ls1, 2);
        s0  += __shfl_xor_sync(0xFFFFFFFFu, s0, 1);
        s0  += __shfl_xor_sync(0xFFFFFFFFu, s0, 2);
        s1  += __shfl_xor_sync(0xFFFFFFFFu, s1, 1);
        s1  += __shfl_xor_sync(0xFFFFFFFFu, s1, 2);
        if (tig == 0) {
            if (pA < PPV)     { slog[pA] = ls0;     ssv[pA] = s0; }
            if (pA + 8 < PPV) { slog[pA + 8] = ls1; ssv[pA + 8] = s1; }
        }
    }
    __syncthreads();

    // ---- softmax over 780 pairs + weighted sum ----
    float lmax = -INFINITY;
    for (int pp = tid; pp < PPV; pp += NTH) lmax = fmaxf(lmax, slog[pp]);
    #pragma unroll
    for (int o = 16; o > 0; o >>= 1)
        lmax = fmaxf(lmax, __shfl_xor_sync(0xFFFFFFFFu, lmax, o));
    if (lane == 0) red[wrp] = lmax;
    __syncthreads();
    if (tid == 0) {
        float m = red[0];
        #pragma unroll
        for (int w = 1; w < NW; w++) m = fmaxf(m, red[w]);
        red[16] = m;
    }
    __syncthreads();
    const float mx = red[16];

    float num = 0.0f, den = 0.0f;
    for (int pp = tid; pp < PPV; pp += NTH) {
        float e = __expf(slog[pp] - mx);
        num = fmaf(e, ssv[pp], num);
        den += e;
    }
    #pragma unroll
    for (int o = 16; o > 0; o >>= 1) {
        num += __shfl_xor_sync(0xFFFFFFFFu, num, o);
        den += __shfl_xor_sync(0xFFFFFFFFu, den, o);
    }
    __syncthreads();
    if (lane == 0) { red[wrp] = num; red[8 + wrp] = den; }
    __syncthreads();
    if (tid == 0) {
        float n = 0.0f, d = 0.0f;
        #pragma unroll
        for (int w = 0; w < NW; w++) { n += red[w]; d += red[8 + w]; }
        out[b] = n / d;
    }
}

extern "C" void kernel_launch(void* const* d_in, const int* in_sizes, int n_in,
                              void* d_out, int out_size)
{
    const float* x    = (const float*)d_in[0];
    const float* W1   = (const float*)d_in[1];
    const float* b1   = (const float*)d_in[2];
    const float* w2   = (const float*)d_in[3];
    const float* pvec = (const float*)d_in[4];
    float* out = (float*)d_out;

    int B = in_sizes[0] / (NF * DD);
    afm_kernel<<<B, NTH>>>(x, W1, b1, w2, pvec, out);
}